// round 6
// baseline (speedup 1.0000x reference)
#include <cuda_runtime.h>
#include <cuda_bf16.h>
#include <mma.h>

using namespace nvcuda;

#define BN 8192
#define CDIM 256
#define MT 64
#define NT 64
#define NTHREADS 256
#define KTILES (BN / NT)

// shared memory byte offsets
#define OFF_Q   0        // 64x256 bf16 = 32768
#define OFF_K   32768    // 64x256 bf16 = 32768
#define OFF_S   65536    // 64x64  f32  = 16384
#define OFF_P   81920    // 64x64  bf16 =  8192
#define OFF_DEN 90112    // 64 f32      =   256
#define SMEM_BYTES 90368

// scratch (allocation-free: __device__ globals)
__device__ float         g_f32[BN * CDIM];   // normalized f, fp32 (for blend)
__device__ __nv_bfloat16 g_fbf[BN * CDIM];   // normalized f, bf16 (MMA operands)

// ---------------------------------------------------------------------------
// Kernel 1: row L2-normalize. One warp per row.
// ---------------------------------------------------------------------------
__global__ void __launch_bounds__(256) norm_kernel(const float* __restrict__ in) {
    int row  = blockIdx.x * 8 + (threadIdx.x >> 5);
    int lane = threadIdx.x & 31;
    const float* r = in + (size_t)row * CDIM;
    float v[8];
    float ss = 0.f;
#pragma unroll
    for (int i = 0; i < 8; i++) { v[i] = r[lane + 32 * i]; ss = fmaf(v[i], v[i], ss); }
#pragma unroll
    for (int o = 16; o > 0; o >>= 1) ss += __shfl_xor_sync(0xffffffffu, ss, o);
    float inv = 1.0f / fmaxf(sqrtf(ss), 1e-12f);
    float*         o32 = g_f32 + (size_t)row * CDIM;
    __nv_bfloat16* obf = g_fbf + (size_t)row * CDIM;
#pragma unroll
    for (int i = 0; i < 8; i++) {
        float x = v[i] * inv;
        o32[lane + 32 * i] = x;
        obf[lane + 32 * i] = __float2bfloat16(x);
    }
}

// ---------------------------------------------------------------------------
// Kernel 2: fused attention + blend + renorm.
// CTA = 64 query rows, 8 warps (4x2 layout). Scores bounded in [-1,1] so the
// softmax needs NO max tracking: accumulate exp-rowsum + exp(S)@V directly.
// ---------------------------------------------------------------------------
__global__ void __launch_bounds__(256) attn_kernel(float* __restrict__ out) {
    extern __shared__ char smem[];
    __nv_bfloat16* sQ   = (__nv_bfloat16*)(smem + OFF_Q);
    __nv_bfloat16* sK   = (__nv_bfloat16*)(smem + OFF_K);
    float*         sS   = (float*)(smem + OFF_S);
    __nv_bfloat16* sP   = (__nv_bfloat16*)(smem + OFF_P);
    float*         sDen = (float*)(smem + OFF_DEN);
    float*         sO   = (float*)(smem + OFF_Q);   // epilogue alias over Q+K (64KB)

    const int tid   = threadIdx.x;
    const int wid   = tid >> 5;
    const int lane  = tid & 31;
    const int wm    = wid >> 1;   // 0..3 : 16-row slice of the 64 queries
    const int wn    = wid & 1;    // 0..1 : column half
    const int qbase = blockIdx.x * MT;

    if (tid < MT) sDen[tid] = 0.f;

    // load Q tile (bf16), vectorized 16B
    {
        const uint4* src = (const uint4*)(g_fbf + (size_t)qbase * CDIM);
        uint4*       dst = (uint4*)sQ;
        for (int i = tid; i < MT * CDIM / 8; i += NTHREADS) dst[i] = src[i];
    }

    wmma::fragment<wmma::accumulator, 16, 16, 16, float> oAcc[8];
#pragma unroll
    for (int s = 0; s < 8; s++) wmma::fill_fragment(oAcc[s], 0.0f);

    for (int kt = 0; kt < KTILES; kt++) {
        // load K tile (also serves as V)
        {
            const uint4* src = (const uint4*)(g_fbf + (size_t)kt * NT * CDIM);
            uint4*       dst = (uint4*)sK;
            for (int i = tid; i < NT * CDIM / 8; i += NTHREADS) dst[i] = src[i];
        }
        __syncthreads();

        // ---- S = Q * K^T  (64x64, K-dim 256) ----
        {
            wmma::fragment<wmma::accumulator, 16, 16, 16, float> sAcc[2];
            wmma::fill_fragment(sAcc[0], 0.0f);
            wmma::fill_fragment(sAcc[1], 0.0f);
            wmma::fragment<wmma::matrix_a, 16, 16, 16, __nv_bfloat16, wmma::row_major> a;
            wmma::fragment<wmma::matrix_b, 16, 16, 16, __nv_bfloat16, wmma::col_major> b;
#pragma unroll
            for (int k0 = 0; k0 < CDIM; k0 += 16) {
                wmma::load_matrix_sync(a, sQ + wm * 16 * CDIM + k0, CDIM);
#pragma unroll
                for (int s = 0; s < 2; s++) {
                    // B(k,n) = K[n][k]: col-major view of row-major K, ldm = CDIM
                    wmma::load_matrix_sync(b, sK + (wn * 32 + s * 16) * CDIM + k0, CDIM);
                    wmma::mma_sync(sAcc[s], a, b, sAcc[s]);
                }
            }
#pragma unroll
            for (int s = 0; s < 2; s++)
                wmma::store_matrix_sync(sS + wm * 16 * NT + wn * 32 + s * 16,
                                        sAcc[s], NT, wmma::mem_row_major);
        }
        __syncthreads();

        // ---- P = exp(S) (no max shift: |S| <= 1), denom += rowsum(P) ----
        {
            int r  = tid >> 2;
            int c0 = (tid & 3) << 4;
            float acc = 0.f;
#pragma unroll
            for (int i = 0; i < 16; i++) {
                float e = __expf(sS[r * NT + c0 + i]);
                sP[r * NT + c0 + i] = __float2bfloat16(e);
                acc += e;
            }
            atomicAdd(&sDen[r], acc);
        }
        __syncthreads();

        // ---- O += P * V  (V = K tile, row-major [keys][C]) ----
        {
            wmma::fragment<wmma::matrix_a, 16, 16, 16, __nv_bfloat16, wmma::row_major> a;
            wmma::fragment<wmma::matrix_b, 16, 16, 16, __nv_bfloat16, wmma::row_major> b;
#pragma unroll
            for (int kk = 0; kk < NT; kk += 16) {
                wmma::load_matrix_sync(a, sP + wm * 16 * NT + kk, NT);
#pragma unroll
                for (int s = 0; s < 8; s++) {
                    wmma::load_matrix_sync(b, sK + kk * CDIM + wn * 128 + s * 16, CDIM);
                    wmma::mma_sync(oAcc[s], a, b, oAcc[s]);
                }
            }
        }
        __syncthreads();  // protects sK/sP before next tile, and sO alias below
    }

    // ---- spill O to smem (aliases Q/K, both dead now) ----
#pragma unroll
    for (int s = 0; s < 8; s++)
        wmma::store_matrix_sync(sO + wm * 16 * CDIM + wn * 128 + s * 16,
                                oAcc[s], CDIM, wmma::mem_row_major);
    __syncthreads();

    // ---- blend + renormalize: 8 rows per warp ----
#pragma unroll
    for (int j = 0; j < 8; j++) {
        int row = wid * 8 + j;
        float invd = 0.2f / sDen[row];
        const float* frow = g_f32 + (size_t)(qbase + row) * CDIM;
        float b[8], ss = 0.f;
#pragma unroll
        for (int i = 0; i < 8; i++) {
            int c = lane + 32 * i;
            float x = fmaf(0.8f, frow[c], sO[row * CDIM + c] * invd);
            b[i] = x;
            ss = fmaf(x, x, ss);
        }
#pragma unroll
        for (int o = 16; o > 0; o >>= 1) ss += __shfl_xor_sync(0xffffffffu, ss, o);
        float inv = 1.0f / fmaxf(sqrtf(ss), 1e-12f);
        float* orow = out + (size_t)(qbase + row) * CDIM;
#pragma unroll
        for (int i = 0; i < 8; i++) orow[lane + 32 * i] = b[i] * inv;
    }
}

// ---------------------------------------------------------------------------
extern "C" void kernel_launch(void* const* d_in, const int* in_sizes, int n_in,
                              void* d_out, int out_size) {
    const float* feats = (const float*)d_in[0];
    float*       out   = (float*)d_out;
    (void)in_sizes; (void)n_in; (void)out_size;

    // idempotent, deterministic, capture-safe (not a stream op)
    cudaFuncSetAttribute(attn_kernel,
                         cudaFuncAttributeMaxDynamicSharedMemorySize, SMEM_BYTES);

    norm_kernel<<<BN / 8, 256>>>(feats);
    attn_kernel<<<BN / MT, 256, SMEM_BYTES>>>(out);
}

// round 8
// speedup vs baseline: 6.1603x; 6.1603x over previous
#include <cuda_runtime.h>
#include <cuda_bf16.h>
#include <cstdint>

#define BN 8192
#define CDIM 256
#define MT 64
#define NT 64
#define TTILES (BN / NT)   // 128
#define ROWB 512           // smem bytes per tile row (256 bf16)

#define SQ_OFF  0
#define SK0_OFF 32768
#define SK1_OFF 65536
#define SMEM_TOTAL 98304   // 96KB

__device__ float         g_f32[BN * CDIM];   // normalized f (fp32, for blend)
__device__ __nv_bfloat16 g_fbf[BN * CDIM];   // normalized f (bf16, MMA operand)

// ---------------------------------------------------------------- helpers
__device__ __forceinline__ uint32_t smem_u32(const void* p) {
    uint32_t a;
    asm("{ .reg .u64 t; cvta.to.shared.u64 t, %1; cvt.u32.u64 %0, t; }" : "=r"(a) : "l"(p));
    return a;
}
__device__ __forceinline__ void cp16(uint32_t dst, const void* src) {
    asm volatile("cp.async.cg.shared.global [%0], [%1], 16;" :: "r"(dst), "l"(src));
}
#define CP_COMMIT() asm volatile("cp.async.commit_group;" ::: "memory")

__device__ __forceinline__ void ldsm4(uint32_t a, uint32_t& r0, uint32_t& r1,
                                      uint32_t& r2, uint32_t& r3) {
    asm volatile("ldmatrix.sync.aligned.m8n8.x4.shared.b16 {%0,%1,%2,%3}, [%4];"
                 : "=r"(r0), "=r"(r1), "=r"(r2), "=r"(r3) : "r"(a));
}
__device__ __forceinline__ void ldsm4t(uint32_t a, uint32_t& r0, uint32_t& r1,
                                       uint32_t& r2, uint32_t& r3) {
    asm volatile("ldmatrix.sync.aligned.m8n8.x4.trans.shared.b16 {%0,%1,%2,%3}, [%4];"
                 : "=r"(r0), "=r"(r1), "=r"(r2), "=r"(r3) : "r"(a));
}
__device__ __forceinline__ void mma16816(float (&c)[4], uint32_t a0, uint32_t a1,
                                         uint32_t a2, uint32_t a3,
                                         uint32_t b0, uint32_t b1) {
    asm volatile("mma.sync.aligned.m16n8k16.row.col.f32.bf16.bf16.f32 "
                 "{%0,%1,%2,%3}, {%4,%5,%6,%7}, {%8,%9}, {%0,%1,%2,%3};"
                 : "+f"(c[0]), "+f"(c[1]), "+f"(c[2]), "+f"(c[3])
                 : "r"(a0), "r"(a1), "r"(a2), "r"(a3), "r"(b0), "r"(b1));
}

// Load a 64x256 bf16 tile into smem, 512B rows, XOR-swizzled 16B units.
__device__ __forceinline__ void load_tile(uint32_t dst, const __nv_bfloat16* src, int tid) {
#pragma unroll
    for (int q = 0; q < 16; q++) {
        int i   = tid + q * 128;
        int row = i >> 5;
        int u   = i & 31;
        uint32_t d = dst + row * ROWB + ((u << 4) ^ ((row & 7) << 4));
        cp16(d, src + (size_t)row * CDIM + u * 8);
    }
}

// ---------------------------------------------------------------------------
// Kernel 1: row L2-normalize (unchanged)
// ---------------------------------------------------------------------------
__global__ void __launch_bounds__(256) norm_kernel(const float* __restrict__ in) {
    int row  = blockIdx.x * 8 + (threadIdx.x >> 5);
    int lane = threadIdx.x & 31;
    const float* r = in + (size_t)row * CDIM;
    float v[8]; float ss = 0.f;
#pragma unroll
    for (int i = 0; i < 8; i++) { v[i] = r[lane + 32 * i]; ss = fmaf(v[i], v[i], ss); }
#pragma unroll
    for (int o = 16; o > 0; o >>= 1) ss += __shfl_xor_sync(0xffffffffu, ss, o);
    float inv = 1.0f / fmaxf(sqrtf(ss), 1e-12f);
    float*         o32 = g_f32 + (size_t)row * CDIM;
    __nv_bfloat16* obf = g_fbf + (size_t)row * CDIM;
#pragma unroll
    for (int i = 0; i < 8; i++) {
        float x = v[i] * inv;
        o32[lane + 32 * i] = x;
        obf[lane + 32 * i] = __float2bfloat16(x);
    }
}

// ---------------------------------------------------------------------------
// Kernel 2: FA2-style fused attention. grid=128, block=128 (4 warps),
// each warp owns 16 query rows, O resident in registers (16x256 f32).
// Scores in [-1,1] -> softmax needs no max tracking.
// ---------------------------------------------------------------------------
__global__ void __launch_bounds__(128, 1) attn_kernel(float* __restrict__ out) {
    extern __shared__ char smem[];
    const uint32_t sb = smem_u32(smem);
    const int tid  = threadIdx.x;
    const int lane = tid & 31;
    const int wm   = tid >> 5;
    const int g    = lane >> 2;
    const int tg   = lane & 3;
    const int qbase = blockIdx.x * MT;

    // prologue: Q + K0 (group 0), K1 (group 1)
    load_tile(sb + SQ_OFF,  g_fbf + (size_t)qbase * CDIM, tid);
    load_tile(sb + SK0_OFF, g_fbf, tid);
    CP_COMMIT();
    load_tile(sb + SK1_OFF, g_fbf + (size_t)NT * CDIM, tid);
    CP_COMMIT();

    // per-thread ldmatrix address components
    const int rowA = wm * 16 + (lane & 15);                  // A: Q rows
    const uint32_t aBase = sb + SQ_OFF + rowA * ROWB;
    const int chA = (lane >> 4) << 4, swzA = (rowA & 7) << 4;

    const int rowB0 = (lane & 7) + ((lane >> 4) << 3);       // B (S): key rows
    const int chB = ((lane >> 3) & 1) << 4, swzB = (lane & 7) << 4;

    const int rowV0 = (lane & 7) + (((lane >> 3) & 1) << 3); // B (V, trans): key rows
    const int chV = (lane >> 4) << 4, swzV = (lane & 7) << 4;

    float O[32][4];
#pragma unroll
    for (int j = 0; j < 32; j++) { O[j][0] = O[j][1] = O[j][2] = O[j][3] = 0.f; }
    float d0 = 0.f, d1 = 0.f;   // exp-rowsums for rows g and g+8

#pragma unroll 1
    for (int t = 0; t < TTILES; t++) {
        if (t == TTILES - 1) asm volatile("cp.async.wait_group 0;" ::: "memory");
        else                 asm volatile("cp.async.wait_group 1;" ::: "memory");
        __syncthreads();
        const uint32_t kbuf = sb + ((t & 1) ? SK1_OFF : SK0_OFF);

        // ---- S = Q @ K^T  (16x64 per warp, registers) ----
        float S[8][4];
#pragma unroll
        for (int j = 0; j < 8; j++) S[j][0] = S[j][1] = S[j][2] = S[j][3] = 0.f;
#pragma unroll
        for (int ks = 0; ks < 16; ks++) {
            uint32_t a0, a1, a2, a3;
            ldsm4(aBase + (uint32_t)((chA + 32 * ks) ^ swzA), a0, a1, a2, a3);
#pragma unroll
            for (int j = 0; j < 4; j++) {
                uint32_t b0, b1, b2, b3;
                ldsm4(kbuf + (rowB0 + 16 * j) * ROWB + (uint32_t)((chB + 32 * ks) ^ swzB),
                      b0, b1, b2, b3);
                mma16816(S[2 * j],     a0, a1, a2, a3, b0, b1);
                mma16816(S[2 * j + 1], a0, a1, a2, a3, b2, b3);
            }
        }

        // ---- P = exp(S) in registers; repack as A-fragments (FA2 identity) ----
        uint32_t P[4][4];
#pragma unroll
        for (int j = 0; j < 8; j++) {
            float e0 = __expf(S[j][0]), e1 = __expf(S[j][1]);
            float e2 = __expf(S[j][2]), e3 = __expf(S[j][3]);
            d0 += e0 + e1;  d1 += e2 + e3;
            uint32_t plo, phi;
            asm("cvt.rn.bf16x2.f32 %0, %1, %2;" : "=r"(plo) : "f"(e1), "f"(e0));
            asm("cvt.rn.bf16x2.f32 %0, %1, %2;" : "=r"(phi) : "f"(e3), "f"(e2));
            P[j >> 1][(j & 1) * 2 + 0] = plo;
            P[j >> 1][(j & 1) * 2 + 1] = phi;
        }

        // ---- O += P @ V  (V = same K tile, ldmatrix.trans) ----
#pragma unroll
        for (int kb = 0; kb < 4; kb++) {
            const uint32_t vrow = kbuf + (rowV0 + 16 * kb) * ROWB;
#pragma unroll
            for (int nq = 0; nq < 16; nq++) {
                uint32_t b0, b1, b2, b3;
                ldsm4t(vrow + (uint32_t)((chV + 32 * nq) ^ swzV), b0, b1, b2, b3);
                mma16816(O[2 * nq],     P[kb][0], P[kb][1], P[kb][2], P[kb][3], b0, b1);
                mma16816(O[2 * nq + 1], P[kb][0], P[kb][1], P[kb][2], P[kb][3], b2, b3);
            }
        }

        __syncthreads();   // all warps done reading the buffer we're about to refill
        if (t + 2 < TTILES) {
            load_tile(sb + ((t & 1) ? SK1_OFF : SK0_OFF),
                      g_fbf + (size_t)(t + 2) * NT * CDIM, tid);
            CP_COMMIT();
        }
    }

    // ---- denominators: reduce across the 4 threads sharing a row ----
#pragma unroll
    for (int off = 1; off <= 2; off <<= 1) {
        d0 += __shfl_xor_sync(0xffffffffu, d0, off);
        d1 += __shfl_xor_sync(0xffffffffu, d1, off);
    }
    const float invd0 = 0.2f / d0;
    const float invd1 = 0.2f / d1;

    // ---- blend with f, then row renorm ----
    const int r0 = qbase + wm * 16 + g, r1 = r0 + 8;
    const float* f0 = g_f32 + (size_t)r0 * CDIM;
    const float* f1 = g_f32 + (size_t)r1 * CDIM;
    float ss0 = 0.f, ss1 = 0.f;
#pragma unroll
    for (int j = 0; j < 32; j++) {
        int col = 8 * j + 2 * tg;
        float2 fa = *(const float2*)(f0 + col);
        float2 fb = *(const float2*)(f1 + col);
        O[j][0] = fmaf(0.8f, fa.x, invd0 * O[j][0]);
        O[j][1] = fmaf(0.8f, fa.y, invd0 * O[j][1]);
        O[j][2] = fmaf(0.8f, fb.x, invd1 * O[j][2]);
        O[j][3] = fmaf(0.8f, fb.y, invd1 * O[j][3]);
        ss0 = fmaf(O[j][0], O[j][0], fmaf(O[j][1], O[j][1], ss0));
        ss1 = fmaf(O[j][2], O[j][2], fmaf(O[j][3], O[j][3], ss1));
    }
#pragma unroll
    for (int off = 1; off <= 2; off <<= 1) {
        ss0 += __shfl_xor_sync(0xffffffffu, ss0, off);
        ss1 += __shfl_xor_sync(0xffffffffu, ss1, off);
    }
    const float inv0 = 1.0f / fmaxf(sqrtf(ss0), 1e-12f);
    const float inv1 = 1.0f / fmaxf(sqrtf(ss1), 1e-12f);
    float* o0 = out + (size_t)r0 * CDIM;
    float* o1 = out + (size_t)r1 * CDIM;
#pragma unroll
    for (int j = 0; j < 32; j++) {
        int col = 8 * j + 2 * tg;
        *(float2*)(o0 + col) = make_float2(O[j][0] * inv0, O[j][1] * inv0);
        *(float2*)(o1 + col) = make_float2(O[j][2] * inv1, O[j][3] * inv1);
    }
}

// ---------------------------------------------------------------------------
extern "C" void kernel_launch(void* const* d_in, const int* in_sizes, int n_in,
                              void* d_out, int out_size) {
    const float* feats = (const float*)d_in[0];
    float*       out   = (float*)d_out;
    (void)in_sizes; (void)n_in; (void)out_size;

    cudaFuncSetAttribute(attn_kernel,
                         cudaFuncAttributeMaxDynamicSharedMemorySize, SMEM_TOTAL);

    norm_kernel<<<BN / 8, 256>>>(feats);
    attn_kernel<<<BN / MT, 128, SMEM_TOTAL>>>(out);
}

// round 9
// speedup vs baseline: 7.6494x; 1.2417x over previous
#include <cuda_runtime.h>
#include <cuda_bf16.h>
#include <cstdint>

#define BN 8192
#define CDIM 256
#define MT 64
#define NT 64
#define TTILES (BN / NT)   // 128
#define ITERS (TTILES / 2) // 64: each iteration = one even + one odd tile
#define ROWB 512           // smem bytes per tile row (256 bf16)

#define SQ_OFF 0
#define SK_OFF 32768              // 2 slots x 64KB (pair of tiles each)
#define PAIR_BYTES 65536
#define SMEM_TOTAL (32768 + 2 * PAIR_BYTES)   // 163840
// epilogue overlays (K region is dead by then)
#define OFF_OX  32768             // O exchange: 64 rows x 256 f32 = 64KB
#define OFF_DN  (32768 + 65536)   // 64 f32 denominators

__device__ float         g_f32[BN * CDIM];   // normalized f (fp32, for blend)
__device__ __nv_bfloat16 g_fbf[BN * CDIM];   // normalized f (bf16, MMA operand)

// ---------------------------------------------------------------- helpers
__device__ __forceinline__ uint32_t smem_u32(const void* p) {
    uint32_t a;
    asm("{ .reg .u64 t; cvta.to.shared.u64 t, %1; cvt.u32.u64 %0, t; }" : "=r"(a) : "l"(p));
    return a;
}
__device__ __forceinline__ void cp16(uint32_t dst, const void* src) {
    asm volatile("cp.async.cg.shared.global [%0], [%1], 16;" :: "r"(dst), "l"(src));
}
#define CP_COMMIT() asm volatile("cp.async.commit_group;" ::: "memory")

__device__ __forceinline__ void ldsm4(uint32_t a, uint32_t& r0, uint32_t& r1,
                                      uint32_t& r2, uint32_t& r3) {
    asm volatile("ldmatrix.sync.aligned.m8n8.x4.shared.b16 {%0,%1,%2,%3}, [%4];"
                 : "=r"(r0), "=r"(r1), "=r"(r2), "=r"(r3) : "r"(a));
}
__device__ __forceinline__ void ldsm4t(uint32_t a, uint32_t& r0, uint32_t& r1,
                                       uint32_t& r2, uint32_t& r3) {
    asm volatile("ldmatrix.sync.aligned.m8n8.x4.trans.shared.b16 {%0,%1,%2,%3}, [%4];"
                 : "=r"(r0), "=r"(r1), "=r"(r2), "=r"(r3) : "r"(a));
}
__device__ __forceinline__ void mma16816(float (&c)[4], uint32_t a0, uint32_t a1,
                                         uint32_t a2, uint32_t a3,
                                         uint32_t b0, uint32_t b1) {
    asm volatile("mma.sync.aligned.m16n8k16.row.col.f32.bf16.bf16.f32 "
                 "{%0,%1,%2,%3}, {%4,%5,%6,%7}, {%8,%9}, {%0,%1,%2,%3};"
                 : "+f"(c[0]), "+f"(c[1]), "+f"(c[2]), "+f"(c[3])
                 : "r"(a0), "r"(a1), "r"(a2), "r"(a3), "r"(b0), "r"(b1));
}

// Load `rows` tile rows (256 bf16 each) into smem, 512B rows, XOR swizzle,
// spread over 256 threads. rows*32 chunks of 16B.
template <int ROWS>
__device__ __forceinline__ void load_rows(uint32_t dst, const __nv_bfloat16* src, int tid) {
#pragma unroll
    for (int q = 0; q < ROWS * 32 / 256; q++) {
        int i   = tid + q * 256;
        int row = i >> 5;
        int u   = i & 31;
        uint32_t d = dst + row * ROWB + ((u << 4) ^ ((row & 7) << 4));
        cp16(d, src + (size_t)row * CDIM + u * 8);
    }
}

// ---------------------------------------------------------------------------
// Kernel 1: row L2-normalize
// ---------------------------------------------------------------------------
__global__ void __launch_bounds__(256) norm_kernel(const float* __restrict__ in) {
    int row  = blockIdx.x * 8 + (threadIdx.x >> 5);
    int lane = threadIdx.x & 31;
    const float* r = in + (size_t)row * CDIM;
    float v[8]; float ss = 0.f;
#pragma unroll
    for (int i = 0; i < 8; i++) { v[i] = r[lane + 32 * i]; ss = fmaf(v[i], v[i], ss); }
#pragma unroll
    for (int o = 16; o > 0; o >>= 1) ss += __shfl_xor_sync(0xffffffffu, ss, o);
    float inv = 1.0f / fmaxf(sqrtf(ss), 1e-12f);
    float*         o32 = g_f32 + (size_t)row * CDIM;
    __nv_bfloat16* obf = g_fbf + (size_t)row * CDIM;
#pragma unroll
    for (int i = 0; i < 8; i++) {
        float x = v[i] * inv;
        o32[lane + 32 * i] = x;
        obf[lane + 32 * i] = __float2bfloat16(x);
    }
}

// ---------------------------------------------------------------------------
// Kernel 2: FA2-style fused attention, 8 warps = 2 key-split groups.
// Group gg (wid>>2) handles key tiles {2*it+gg}. Each of its 4 warps owns 16
// query rows with O (16x256 f32) in registers. Partial O/denoms combined via
// smem at the end. Scores in [-1,1] -> no softmax max tracking.
// ---------------------------------------------------------------------------
__global__ void __launch_bounds__(256, 1) attn_kernel(float* __restrict__ out) {
    extern __shared__ char smem[];
    const uint32_t sb = smem_u32(smem);
    const int tid  = threadIdx.x;
    const int lane = tid & 31;
    const int wid  = tid >> 5;
    const int wm   = wid & 3;     // warp-in-group: 16-row slice
    const int gg   = wid >> 2;    // key group 0/1
    const int g    = lane >> 2;
    const int tg   = lane & 3;
    const int qbase = blockIdx.x * MT;

    // prologue: Q, then two tile-pairs (slot0 = tiles 0,1; slot1 = tiles 2,3)
    load_rows<64>(sb + SQ_OFF, g_fbf + (size_t)qbase * CDIM, tid);
    load_rows<128>(sb + SK_OFF, g_fbf, tid);                             CP_COMMIT();
    load_rows<128>(sb + SK_OFF + PAIR_BYTES, g_fbf + (size_t)128 * CDIM, tid); CP_COMMIT();

    // per-thread ldmatrix address components
    const int rowA = wm * 16 + (lane & 15);
    const uint32_t aBase = sb + SQ_OFF + rowA * ROWB;
    const int chA = (lane >> 4) << 4, swzA = (rowA & 7) << 4;

    const int rowB0 = (lane & 7) + ((lane >> 4) << 3);
    const int chB = ((lane >> 3) & 1) << 4, swzB = (lane & 7) << 4;

    const int rowV0 = (lane & 7) + (((lane >> 3) & 1) << 3);
    const int chV = (lane >> 4) << 4, swzV = (lane & 7) << 4;

    float O[32][4];
#pragma unroll
    for (int j = 0; j < 32; j++) { O[j][0] = O[j][1] = O[j][2] = O[j][3] = 0.f; }
    float d0 = 0.f, d1 = 0.f;

#pragma unroll 1
    for (int it = 0; it < ITERS; it++) {
        if (it == ITERS - 1) asm volatile("cp.async.wait_group 0;" ::: "memory");
        else                 asm volatile("cp.async.wait_group 1;" ::: "memory");
        __syncthreads();
        const uint32_t kbuf = sb + SK_OFF + (uint32_t)(it & 1) * PAIR_BYTES
                                 + (uint32_t)gg * 32768;

        // ---- S = Q @ K^T  (16x64 per warp, registers) ----
        float S[8][4];
#pragma unroll
        for (int j = 0; j < 8; j++) S[j][0] = S[j][1] = S[j][2] = S[j][3] = 0.f;
#pragma unroll
        for (int ks = 0; ks < 16; ks++) {
            uint32_t a0, a1, a2, a3;
            ldsm4(aBase + (uint32_t)((chA + 32 * ks) ^ swzA), a0, a1, a2, a3);
#pragma unroll
            for (int j = 0; j < 4; j++) {
                uint32_t b0, b1, b2, b3;
                ldsm4(kbuf + (rowB0 + 16 * j) * ROWB + (uint32_t)((chB + 32 * ks) ^ swzB),
                      b0, b1, b2, b3);
                mma16816(S[2 * j],     a0, a1, a2, a3, b0, b1);
                mma16816(S[2 * j + 1], a0, a1, a2, a3, b2, b3);
            }
        }

        // ---- P = exp(S) in registers; repack as A-fragments ----
        uint32_t P[4][4];
#pragma unroll
        for (int j = 0; j < 8; j++) {
            float e0 = __expf(S[j][0]), e1 = __expf(S[j][1]);
            float e2 = __expf(S[j][2]), e3 = __expf(S[j][3]);
            d0 += e0 + e1;  d1 += e2 + e3;
            uint32_t plo, phi;
            asm("cvt.rn.bf16x2.f32 %0, %1, %2;" : "=r"(plo) : "f"(e1), "f"(e0));
            asm("cvt.rn.bf16x2.f32 %0, %1, %2;" : "=r"(phi) : "f"(e3), "f"(e2));
            P[j >> 1][(j & 1) * 2 + 0] = plo;
            P[j >> 1][(j & 1) * 2 + 1] = phi;
        }

        // ---- O += P @ V  (V = same K tile, ldmatrix.trans) ----
#pragma unroll
        for (int kb = 0; kb < 4; kb++) {
            const uint32_t vrow = kbuf + (rowV0 + 16 * kb) * ROWB;
#pragma unroll
            for (int nq = 0; nq < 16; nq++) {
                uint32_t b0, b1, b2, b3;
                ldsm4t(vrow + (uint32_t)((chV + 32 * nq) ^ swzV), b0, b1, b2, b3);
                mma16816(O[2 * nq],     P[kb][0], P[kb][1], P[kb][2], P[kb][3], b0, b1);
                mma16816(O[2 * nq + 1], P[kb][0], P[kb][1], P[kb][2], P[kb][3], b2, b3);
            }
        }

        __syncthreads();
        if (it + 2 < ITERS) {
            load_rows<128>(sb + SK_OFF + (uint32_t)(it & 1) * PAIR_BYTES,
                           g_fbf + (size_t)(it + 2) * 128 * CDIM, tid);
            CP_COMMIT();
        }
    }

    // ---- denominators: reduce across the 4 threads sharing a row ----
#pragma unroll
    for (int off = 1; off <= 2; off <<= 1) {
        d0 += __shfl_xor_sync(0xffffffffu, d0, off);
        d1 += __shfl_xor_sync(0xffffffffu, d1, off);
    }

    // ---- combine the two key-groups' partials via smem ----
    float* sOX = (float*)(smem + OFF_OX);
    float* sDN = (float*)(smem + OFF_DN);
    const int r0l = wm * 16 + g;            // local rows this thread owns
    const int r1l = r0l + 8;

    if (gg == 1) {
#pragma unroll
        for (int j = 0; j < 32; j++) {
            int col = 8 * j + 2 * tg;
            *(float2*)(sOX + r0l * CDIM + col) = make_float2(O[j][0], O[j][1]);
            *(float2*)(sOX + r1l * CDIM + col) = make_float2(O[j][2], O[j][3]);
        }
        if (tg == 0) { sDN[r0l] = d0; sDN[r1l] = d1; }
    }
    __syncthreads();
    if (gg == 0) {
        const float invd0 = 0.2f / (d0 + sDN[r0l]);
        const float invd1 = 0.2f / (d1 + sDN[r1l]);
        const float* f0 = g_f32 + (size_t)(qbase + r0l) * CDIM;
        const float* f1 = g_f32 + (size_t)(qbase + r1l) * CDIM;
        float ss0 = 0.f, ss1 = 0.f;
#pragma unroll
        for (int j = 0; j < 32; j++) {
            int col = 8 * j + 2 * tg;
            float2 xa = *(const float2*)(sOX + r0l * CDIM + col);
            float2 xb = *(const float2*)(sOX + r1l * CDIM + col);
            float2 fa = *(const float2*)(f0 + col);
            float2 fb = *(const float2*)(f1 + col);
            O[j][0] = fmaf(0.8f, fa.x, invd0 * (O[j][0] + xa.x));
            O[j][1] = fmaf(0.8f, fa.y, invd0 * (O[j][1] + xa.y));
            O[j][2] = fmaf(0.8f, fb.x, invd1 * (O[j][2] + xb.x));
            O[j][3] = fmaf(0.8f, fb.y, invd1 * (O[j][3] + xb.y));
            ss0 = fmaf(O[j][0], O[j][0], fmaf(O[j][1], O[j][1], ss0));
            ss1 = fmaf(O[j][2], O[j][2], fmaf(O[j][3], O[j][3], ss1));
        }
#pragma unroll
        for (int off = 1; off <= 2; off <<= 1) {
            ss0 += __shfl_xor_sync(0xffffffffu, ss0, off);
            ss1 += __shfl_xor_sync(0xffffffffu, ss1, off);
        }
        const float inv0 = 1.0f / fmaxf(sqrtf(ss0), 1e-12f);
        const float inv1 = 1.0f / fmaxf(sqrtf(ss1), 1e-12f);
        float* o0 = out + (size_t)(qbase + r0l) * CDIM;
        float* o1 = out + (size_t)(qbase + r1l) * CDIM;
#pragma unroll
        for (int j = 0; j < 32; j++) {
            int col = 8 * j + 2 * tg;
            *(float2*)(o0 + col) = make_float2(O[j][0] * inv0, O[j][1] * inv0);
            *(float2*)(o1 + col) = make_float2(O[j][2] * inv1, O[j][3] * inv1);
        }
    }
}

// ---------------------------------------------------------------------------
extern "C" void kernel_launch(void* const* d_in, const int* in_sizes, int n_in,
                              void* d_out, int out_size) {
    const float* feats = (const float*)d_in[0];
    float*       out   = (float*)d_out;
    (void)in_sizes; (void)n_in; (void)out_size;

    cudaFuncSetAttribute(attn_kernel,
                         cudaFuncAttributeMaxDynamicSharedMemorySize, SMEM_TOTAL);

    norm_kernel<<<BN / 8, 256>>>(feats);
    attn_kernel<<<BN / MT, 256, SMEM_TOTAL>>>(out);
}